// round 6
// baseline (speedup 1.0000x reference)
#include <cuda_runtime.h>
#include <cstdint>
#include <cmath>

#define EPS_F 1e-8f
#define TAU_CROSS 1e-4f

// ---------------- scratch (__device__ globals; no allocation allowed) ----------------
__device__ float g_proc[16777216];             // [64][512][512] gathered top-512 rows
__device__ float g_rn2[32768];                 // [64][512] 1/||proc row||
__device__ unsigned long long g_t2[196608];    // [48*512][4 ct][2] per-tile top-2 keys
__device__ unsigned long long g_best[24576];   // [48][512] winning key (low32 = 0xFFFFFFFF-m)
__device__ unsigned long long g_rlist[24576];  // [48][512] flagged rows: n<<32|m1<<16|m2
__device__ int g_rcnt[48];

__device__ __forceinline__ unsigned int fsort(float f) {
    unsigned int u = __float_as_uint(f);
    return u ^ ((unsigned int)((int)u >> 31) | 0x80000000u);
}
__device__ __forceinline__ float finv(unsigned int u) {
    return __uint_as_float((u & 0x80000000u) ? (u ^ 0x80000000u) : ~u);
}
__device__ __forceinline__ void fma2(unsigned long long &c, unsigned long long a, unsigned long long b) {
    asm volatile("fma.rn.f32x2 %0, %1, %2, %0;" : "+l"(c) : "l"(a), "l"(b));
}
__device__ __forceinline__ void top2_upd(unsigned long long &b1, unsigned long long &b2,
                                         unsigned long long k) {
    if (k > b1) { b2 = b1; b1 = k; }
    else if (k > b2) b2 = k;
}
__device__ __forceinline__ void top2_merge(unsigned long long &b1, unsigned long long &b2,
                                           unsigned long long q1, unsigned long long q2) {
    unsigned long long hi = b1 > q1 ? b1 : q1;
    unsigned long long lo = b1 > q1 ? q1 : b1;
    unsigned long long m2 = b2 > q2 ? b2 : q2;
    b1 = hi;
    b2 = lo > m2 ? lo : m2;
}

// ---------------- K init ----------------
__global__ void k_init() {
    int i = blockIdx.x * blockDim.x + threadIdx.x;
    if (i < 48) g_rcnt[i] = 0;
}

// ---------------- K0: scores -> fp32-quantized softmax weights -> top-512 -> gather ----
// Ordering key is the fp32-ROUNDED weight (computed in fp64), index asc on bitwise ties.
// This reproduces XLA's top_k-on-softmax collision semantics (softmax is monotone in
// exact math but fp32 exp quantizes near-equal scores into exact ties -> index order).
__global__ void __launch_bounds__(1024) k_scores(const float* __restrict__ clips,
                                                 const float* __restrict__ W) {
    __shared__ float sW[512];
    __shared__ float sS[1024];
    __shared__ float redf[1024];
    __shared__ double redd[1024];
    __shared__ unsigned long long keys[1024];
    __shared__ int sidx[512];
    int tid = threadIdx.x;
    int cb = blockIdx.x;
    const float* x = clips + (size_t)cb * (1024 * 512);
    if (tid < 512) sW[tid] = W[tid];
    __syncthreads();

    int warp = tid >> 5, lane = tid & 31;
    for (int tt = 0; tt < 32; tt++) {
        int token = (warp << 5) + tt;
        const float* r = x + (size_t)token * 512;
        float s = 0.f;
#pragma unroll 4
        for (int d = lane; d < 512; d += 32) s += r[d] * sW[d];
#pragma unroll
        for (int o = 16; o; o >>= 1) s += __shfl_xor_sync(0xFFFFFFFFu, s, o);
        if (lane == 0) sS[token] = s;
    }
    __syncthreads();

    // exact fp32 max
    redf[tid] = sS[tid];
    __syncthreads();
    for (int sft = 512; sft; sft >>= 1) {
        if (tid < sft) redf[tid] = fmaxf(redf[tid], redf[tid + sft]);
        __syncthreads();
    }
    float smax = redf[0];

    // fp64 exp + fp64 sum (order-independent common divisor)
    double e = exp((double)sS[tid] - (double)smax);
    redd[tid] = e;
    __syncthreads();
    for (int sft = 512; sft; sft >>= 1) {
        if (tid < sft) redd[tid] += redd[tid + sft];
        __syncthreads();
    }
    double esum = redd[0];

    float w32 = (float)(e / esum);  // the fp32 weight XLA ranks by (ideal rounding)
    keys[tid] = ((unsigned long long)fsort(w32) << 32) |
                (unsigned long long)(tid ^ 0x3FF);  // tie -> lower index first
    __syncthreads();

    // bitonic sort, descending (weight desc, index asc on bitwise ties)
    for (int ks = 2; ks <= 1024; ks <<= 1)
        for (int j = ks >> 1; j > 0; j >>= 1) {
            __syncthreads();
            int i = tid, ixj = i ^ j;
            if (ixj > i) {
                unsigned long long a = keys[i], b = keys[ixj];
                bool sw = ((i & ks) == 0) ? (a < b) : (a > b);
                if (sw) { keys[i] = b; keys[ixj] = a; }
            }
        }
    __syncthreads();
    if (tid < 512) sidx[tid] = ((int)(keys[tid] & 0x3FFu)) ^ 0x3FF;
    __syncthreads();

    float* dst = g_proc + (size_t)cb * (512 * 512);
    int half = tid >> 9;
    int d = tid & 511;
    for (int base = 0; base < 512; base += 2) {
        int j = base + half;
        dst[(size_t)j * 512 + d] = x[(size_t)sidx[j] * 512 + d];
    }
}

// ---------------- K1: inverse norms ----------------
__global__ void k_norms() {
    int warp = threadIdx.x >> 5, lane = threadIdx.x & 31;
    int row = blockIdx.x * 8 + warp;
    const float* r = g_proc + (size_t)row * 512;
    float s = 0.f;
#pragma unroll 4
    for (int d = lane; d < 512; d += 32) { float v = r[d]; s += v * v; }
#pragma unroll
    for (int o = 16; o; o >>= 1) s += __shfl_xor_sync(0xFFFFFFFFu, s, o);
    if (lane == 0) g_rn2[row] = 1.0f / sqrtf(s);
}

// ---------------- K2: cross-pair GEMM + fused per-tile TOP-2 ----------------
__global__ void __launch_bounds__(256, 2) k_cross() {
    int tile = blockIdx.x;
    int pair = tile >> 4;
    int rt = (tile >> 2) & 3;
    int ct = tile & 3;
    const float* x1 = g_proc + (size_t)pair * 262144 + (size_t)rt * 128 * 512;
    const float* x2 = g_proc + (size_t)(pair + 16) * 262144 + (size_t)ct * 128 * 512;

    __shared__ __align__(16) float As2[8][256];
    __shared__ __align__(16) float Bs[8][128];
    __shared__ float sRn[128];

    int tid = threadIdx.x;
    int tx = tid & 15, ty = tid >> 4;
    if (tid < 128) sRn[tid] = g_rn2[(size_t)(pair + 16) * 512 + ct * 128 + tid];

    unsigned long long acc[8][4];
#pragma unroll
    for (int i = 0; i < 8; i++)
#pragma unroll
        for (int j = 0; j < 4; j++) acc[i][j] = 0ull;

    int lr = tid >> 1;
    int lk = (tid & 1) << 2;
    const ulonglong2* A2 = (const ulonglong2*)(&As2[0][0]);  // 64 per kk-row
    const ulonglong2* B2 = (const ulonglong2*)(&Bs[0][0]);   // 32 per kk-row
    const float* pa = x1 + (size_t)lr * 512 + lk;
    const float* pb = x2 + (size_t)lr * 512 + lk;

    float4 va = *(const float4*)(pa);
    float4 vb = *(const float4*)(pb);

    for (int k0 = 0; k0 < 512; k0 += 8) {
        __syncthreads();
        As2[lk + 0][2 * lr] = va.x; As2[lk + 0][2 * lr + 1] = va.x;
        As2[lk + 1][2 * lr] = va.y; As2[lk + 1][2 * lr + 1] = va.y;
        As2[lk + 2][2 * lr] = va.z; As2[lk + 2][2 * lr + 1] = va.z;
        As2[lk + 3][2 * lr] = va.w; As2[lk + 3][2 * lr + 1] = va.w;
        Bs[lk + 0][lr] = vb.x;
        Bs[lk + 1][lr] = vb.y;
        Bs[lk + 2][lr] = vb.z;
        Bs[lk + 3][lr] = vb.w;
        __syncthreads();
        if (k0 + 8 < 512) {
            va = *(const float4*)(pa + k0 + 8);
            vb = *(const float4*)(pb + k0 + 8);
        }
#pragma unroll
        for (int kk = 0; kk < 8; kk++) {
            ulonglong2 a01 = A2[kk * 64 + ty * 4 + 0];
            ulonglong2 a23 = A2[kk * 64 + ty * 4 + 1];
            ulonglong2 a45 = A2[kk * 64 + ty * 4 + 2];
            ulonglong2 a67 = A2[kk * 64 + ty * 4 + 3];
            ulonglong2 b01 = B2[kk * 32 + tx * 2 + 0];
            ulonglong2 b23 = B2[kk * 32 + tx * 2 + 1];
            unsigned long long a[8] = {a01.x, a01.y, a23.x, a23.y, a45.x, a45.y, a67.x, a67.y};
            unsigned long long b[4] = {b01.x, b01.y, b23.x, b23.y};
#pragma unroll
            for (int i = 0; i < 8; i++)
#pragma unroll
                for (int j = 0; j < 4; j++) fma2(acc[i][j], a[i], b[j]);
        }
    }

#pragma unroll
    for (int i = 0; i < 8; i++) {
        int n = rt * 128 + ty * 8 + i;
        unsigned long long b1 = 0ull, b2 = 0ull;
#pragma unroll
        for (int j = 0; j < 4; j++) {
            float lo, hi;
            asm volatile("mov.b64 {%0, %1}, %2;" : "=f"(lo), "=f"(hi) : "l"(acc[i][j]));
            int m0 = tx * 8 + j * 2;
            float v0 = lo * sRn[m0];
            float v1 = hi * sRn[m0 + 1];
            top2_upd(b1, b2, ((unsigned long long)fsort(v0) << 32) |
                             (unsigned long long)(0xFFFFFFFFu - (unsigned)(ct * 128 + m0)));
            top2_upd(b1, b2, ((unsigned long long)fsort(v1) << 32) |
                             (unsigned long long)(0xFFFFFFFFu - (unsigned)(ct * 128 + m0 + 1)));
        }
#pragma unroll
        for (int o = 8; o; o >>= 1) {
            unsigned long long q1 = __shfl_xor_sync(0xFFFFFFFFu, b1, o, 16);
            unsigned long long q2 = __shfl_xor_sync(0xFFFFFFFFu, b2, o, 16);
            top2_merge(b1, b2, q1, q2);
        }
        if (tx == 0) {
            size_t base = (((size_t)pair * 512 + n) * 4 + ct) * 2;
            g_t2[base] = b1;
            g_t2[base + 1] = b2;
        }
    }
}

// ---------------- K2b: global top-2 per row; flag near-ties ----------------
__global__ void k_select() {
    int row = blockIdx.x * 256 + threadIdx.x;  // < 24576
    int pair = row >> 9;
    unsigned long long b1 = 0ull, b2 = 0ull;
#pragma unroll
    for (int ct = 0; ct < 4; ct++) {
        size_t base = ((size_t)row * 4 + ct) * 2;
        top2_merge(b1, b2, g_t2[base], g_t2[base + 1]);
    }
    g_best[row] = b1;
    float v1 = finv((unsigned)(b1 >> 32));
    float v2 = finv((unsigned)(b2 >> 32));
    if (v1 - v2 < TAU_CROSS) {
        int n = row & 511;
        unsigned m1 = ~(unsigned)b1 & 0xFFFFu;
        unsigned m2 = ~(unsigned)b2 & 0xFFFFu;
        int slot = atomicAdd(&g_rcnt[pair], 1);
        g_rlist[(size_t)pair * 512 + slot] =
            ((unsigned long long)n << 32) | ((unsigned long long)m1 << 16) | m2;
    }
}

// ---------------- K2c: fp64 rescue of flagged rows (exact argmax) ----------------
__global__ void __launch_bounds__(256) k_rescue() {
    int pair = blockIdx.x;
    int w = threadIdx.x >> 5, lane = threadIdx.x & 31;
    int cnt = g_rcnt[pair];
    for (int e = w; e < cnt; e += 8) {
        unsigned long long ent = g_rlist[(size_t)pair * 512 + e];
        int n = (int)(ent >> 32);
        int m1 = (int)((ent >> 16) & 0xFFFFu);
        int m2 = (int)(ent & 0xFFFFu);
        const float* a = g_proc + (size_t)pair * 262144 + (size_t)n * 512;
        const float* p1 = g_proc + (size_t)(pair + 16) * 262144 + (size_t)m1 * 512;
        const float* p2 = g_proc + (size_t)(pair + 16) * 262144 + (size_t)m2 * 512;
        double d1 = 0, d2 = 0, q1 = 0, q2 = 0;
        for (int d = lane; d < 512; d += 32) {
            double av = a[d], v1 = p1[d], v2 = p2[d];
            d1 += av * v1; q1 += v1 * v1;
            d2 += av * v2; q2 += v2 * v2;
        }
#pragma unroll
        for (int o = 16; o; o >>= 1) {
            d1 += __shfl_xor_sync(0xFFFFFFFFu, d1, o);
            d2 += __shfl_xor_sync(0xFFFFFFFFu, d2, o);
            q1 += __shfl_xor_sync(0xFFFFFFFFu, q1, o);
            q2 += __shfl_xor_sync(0xFFFFFFFFu, q2, o);
        }
        if (lane == 0) {
            double s1 = d1 * sqrt(q2);
            double s2 = d2 * sqrt(q1);
            int m;
            if (s1 > s2) m = m1;
            else if (s2 > s1) m = m2;
            else m = m1 < m2 ? m1 : m2;
            g_best[(size_t)pair * 512 + n] =
                (0x8000000000000000ull) | (unsigned long long)(0xFFFFFFFFu - (unsigned)m);
        }
    }
}

// ---------------- K3: intra merge (row-0 sims, top-256 set, mean) + output ----------------
__global__ void __launch_bounds__(512) k_intra(float* __restrict__ out) {
    int p = blockIdx.x;
    const float* x1 = g_proc + (size_t)p * 262144;
    const float* x2 = g_proc + (size_t)(p + 16) * 262144;
    __shared__ float pm0[512];
    __shared__ float cdot[512];
    __shared__ float cn[512];
    __shared__ int stop[512];
    __shared__ unsigned long long keys[512];
    int tid = threadIdx.x;

    stop[tid] = (int)(0xFFFFFFFFu - (unsigned)g_best[(size_t)p * 512 + tid]);
    __syncthreads();
    int t0 = stop[0];
    pm0[tid] = 0.5f * (x1[(size_t)t0 * 512 + tid] + x2[(size_t)t0 * 512 + tid]);
    __syncthreads();

    int warp = tid >> 5, lane = tid & 31;
    for (int j = warp; j < 512; j += 16) {
        const float* r1 = x1 + (size_t)j * 512;
        const float* r2 = x2 + (size_t)j * 512;
        float sd = 0.f, sn = 0.f;
#pragma unroll 4
        for (int d = lane; d < 512; d += 32) {
            float v = 0.5f * (r1[d] + r2[d]);
            sd += pm0[d] * v;
            sn += v * v;
        }
#pragma unroll
        for (int o = 16; o; o >>= 1) {
            sd += __shfl_xor_sync(0xFFFFFFFFu, sd, o);
            sn += __shfl_xor_sync(0xFFFFFFFFu, sn, o);
        }
        if (lane == 0) { cdot[j] = sd; cn[j] = sqrtf(sn); }
    }
    __syncthreads();

    float n0 = cn[t0];
    {
        int t = stop[tid];
        float v = cdot[t] / fmaxf(n0 * cn[t], EPS_F);
        keys[tid] = ((unsigned long long)fsort(v) << 32) |
                    (unsigned long long)(0xFFFFFFFFu - (unsigned)tid);
    }

    for (int ks = 2; ks <= 512; ks <<= 1)
        for (int j = ks >> 1; j > 0; j >>= 1) {
            __syncthreads();
            int i = tid, ixj = i ^ j;
            if (ixj > i) {
                unsigned long long a = keys[i], b = keys[ixj];
                bool sw = ((i & ks) == 0) ? (a < b) : (a > b);
                if (sw) { keys[i] = b; keys[ixj] = a; }
            }
        }
    __syncthreads();

    float accv = 0.f;
    for (int s = 0; s < 256; s++) {
        int mm = (int)(0xFFFFFFFFu - (unsigned)keys[s]);
        int t = stop[mm];
        accv += x1[(size_t)t * 512 + tid] + x2[(size_t)t * 512 + tid];
    }
    out[(size_t)p * 512 + tid] = accv * (0.5f / 256.0f);
}

// ---------------- launch ----------------
extern "C" void kernel_launch(void* const* d_in, const int* in_sizes, int n_in,
                              void* d_out, int out_size) {
    const float* clips = (const float*)d_in[0];
    const float* W     = (const float*)d_in[1];
    (void)in_sizes; (void)n_in; (void)out_size;

    k_init<<<1, 64>>>();
    k_scores<<<64, 1024>>>(clips, W);
    k_norms<<<4096, 256>>>();
    k_cross<<<768, 256>>>();
    k_select<<<96, 256>>>();
    k_rescue<<<48, 256>>>();
    k_intra<<<48, 512>>>((float*)d_out);
}